// round 2
// baseline (speedup 1.0000x reference)
#include <cuda_runtime.h>
#include <cuda_bf16.h>
#include <cstdint>

// Problem constants
#define BB   4096
#define TT   512
#define INF  3
#define HH   128
#define G4   512   // 4*H

// Persistent-kernel geometry
#define ROWS 32          // batch rows per CTA
#define CTAS (BB/ROWS)   // 128
#define THR  256

// ---------------- device scratch (no cudaMalloc allowed) ----------------
__device__ float g_Wt[HH * G4];      // W_hh transposed: [k][j]  (k-major, 256KB)
__device__ float g_b[G4];            // b_ih + b_hh
__device__ float g_h[BB * HH];       // final hidden state
__device__ float g_scale[HH];        // BN fused scale  = rstd*gamma
__device__ float g_shift[HH];        // BN fused shift  = beta - mean*rstd*gamma

// ---------------- MUFU-free fast math ----------------
// 2^t for t in [-30, 30]. Pure FMA/ALU (no MUFU).
__device__ __forceinline__ float fast_exp2(float t) {
    float z  = __fadd_rn(t, 12582912.0f);        // 1.5*2^23 round-to-nearest-int trick
    int   ni = __float_as_int(z);                // = 0x4B400000 + n
    float nf = __fsub_rn(z, 12582912.0f);
    float f  = t - nf;                           // f in [-0.5, 0.5]
    float p  = 0.00015403530f;                   // Taylor of 2^f, deg 6 (rel err ~1e-7)
    p = __fmaf_rn(p, f, 0.00133335581f);
    p = __fmaf_rn(p, f, 0.00961812911f);
    p = __fmaf_rn(p, f, 0.05550410866f);
    p = __fmaf_rn(p, f, 0.24022650700f);
    p = __fmaf_rn(p, f, 0.69314718056f);
    p = __fmaf_rn(p, f, 1.0f);
    return __int_as_float(__float_as_int(p) + ((ni - 0x4B400000) << 23));
}

// 1/d for d > 0 (normal range). Bit-hack seed + 3 Newton -> ~fp32 exact. No MUFU.
__device__ __forceinline__ float fast_rcp(float d) {
    float y = __int_as_float(0x7EF477D5 - __float_as_int(d));
    y = y * __fmaf_rn(-d, y, 2.0f);
    y = y * __fmaf_rn(-d, y, 2.0f);
    y = y * __fmaf_rn(-d, y, 2.0f);
    return y;
}

__device__ __forceinline__ float fsigmoid(float xv) {
    // 1/(1 + 2^(-x*log2e))
    float t = fminf(fmaxf(-1.44269504089f * xv, -30.0f), 30.0f);
    return fast_rcp(1.0f + fast_exp2(t));
}

__device__ __forceinline__ float ftanh(float xv) {
    // 1 - 2/(1 + 2^(2x*log2e))
    float t = fminf(fmaxf(2.88539008178f * xv, -30.0f), 30.0f);
    return __fmaf_rn(-2.0f, fast_rcp(1.0f + fast_exp2(t)), 1.0f);
}

// ---------------- prep: transpose W_hh, fuse biases ----------------
__global__ void prep_kernel(const float* __restrict__ Whh,
                            const float* __restrict__ bih,
                            const float* __restrict__ bhh) {
    int idx = blockIdx.x * blockDim.x + threadIdx.x;
    if (idx < HH * G4) {
        int k = idx >> 9;          // / 512
        int j = idx & 511;
        g_Wt[idx] = Whh[j * HH + k];
    }
    if (idx < G4) g_b[idx] = bih[idx] + bhh[idx];
}

// ---------------- persistent LSTM kernel ----------------
// CTA: 32 batch rows.  Thread (ty, hx): ty = row-group (8 rows), hx -> 2 hidden cols.
// Each thread owns gates z[g][r][cc] for 4 gates x 8 rows x 2 cols, and c in regs.
__global__ void __launch_bounds__(THR, 1) lstm_main(
    const float* __restrict__ x, const float* __restrict__ Wih)
{
    __shared__ float hs[ROWS][HH];   // current h
    __shared__ float xs[ROWS][INF];  // x_t slice

    const int tid = threadIdx.x;
    const int hx  = tid & 63;        // 0..63
    const int ty  = tid >> 6;        // 0..3
    const int hc0 = hx * 2;          // hidden col pair base
    const int r0  = ty * 8;          // row base inside CTA
    const int b0  = blockIdx.x * ROWS;

    // zero h
    for (int i = tid; i < ROWS * HH; i += THR) ((float*)hs)[i] = 0.0f;

    // per-thread constant regs: W_ih rows + bias for my 8 gate-columns
    float wihr[4][2][3];
    float biasr[4][2];
#pragma unroll
    for (int g = 0; g < 4; ++g)
#pragma unroll
        for (int cc = 0; cc < 2; ++cc) {
            int j = g * HH + hc0 + cc;
            biasr[g][cc] = g_b[j];
#pragma unroll
            for (int k = 0; k < INF; ++k) wihr[g][cc][k] = Wih[j * INF + k];
        }

    const int xr = tid / 3;          // valid when tid < 96
    const int xk = tid - xr * 3;
    if (tid < 96) xs[xr][xk] = x[(b0 + xr) * (TT * INF) + xk];  // t = 0
    __syncthreads();

    float cst[8][2];
#pragma unroll
    for (int r = 0; r < 8; ++r) { cst[r][0] = 0.0f; cst[r][1] = 0.0f; }
    float hnew[8][2];

    for (int t = 0; t < TT; ++t) {
        // ---- gate pre-activations ----
        float z[4][8][2];
#pragma unroll
        for (int g = 0; g < 4; ++g)
#pragma unroll
            for (int r = 0; r < 8; ++r) {
                z[g][r][0] = biasr[g][0];
                z[g][r][1] = biasr[g][1];
            }
        // x contribution (3 FMAs per gate element)
#pragma unroll
        for (int r = 0; r < 8; ++r) {
            float x0 = xs[r0 + r][0], x1 = xs[r0 + r][1], x2 = xs[r0 + r][2];
#pragma unroll
            for (int g = 0; g < 4; ++g)
#pragma unroll
                for (int cc = 0; cc < 2; ++cc) {
                    float a = __fmaf_rn(x2, wihr[g][cc][2], z[g][r][cc]);
                    a = __fmaf_rn(x1, wihr[g][cc][1], a);
                    z[g][r][cc] = __fmaf_rn(x0, wihr[g][cc][0], a);
                }
        }
        // h @ W_hh^T : k-loop, 4 k at a time.  h loads are warp-broadcast LDS.128.
#pragma unroll 2
        for (int k4 = 0; k4 < HH; k4 += 4) {
            float4 hv[8];
#pragma unroll
            for (int r = 0; r < 8; ++r)
                hv[r] = *(const float4*)&hs[r0 + r][k4];
#pragma unroll
            for (int kk = 0; kk < 4; ++kk) {
                float2 w[4];
#pragma unroll
                for (int g = 0; g < 4; ++g)
                    w[g] = __ldg((const float2*)&g_Wt[(k4 + kk) * G4 + g * HH + hc0]);
#pragma unroll
                for (int r = 0; r < 8; ++r) {
                    float h_ = (kk == 0) ? hv[r].x : (kk == 1) ? hv[r].y
                             : (kk == 2) ? hv[r].z : hv[r].w;
#pragma unroll
                    for (int g = 0; g < 4; ++g) {
                        z[g][r][0] = __fmaf_rn(h_, w[g].x, z[g][r][0]);
                        z[g][r][1] = __fmaf_rn(h_, w[g].y, z[g][r][1]);
                    }
                }
            }
        }
        // ---- nonlinearities + cell update (MUFU-free) ----
#pragma unroll
        for (int r = 0; r < 8; ++r)
#pragma unroll
            for (int cc = 0; cc < 2; ++cc) {
                float i_ = fsigmoid(z[0][r][cc]);
                float f_ = fsigmoid(z[1][r][cc]);
                float g_ = ftanh   (z[2][r][cc]);
                float o_ = fsigmoid(z[3][r][cc]);
                float cn = __fmaf_rn(f_, cst[r][cc], i_ * g_);
                cst[r][cc]  = cn;
                hnew[r][cc] = o_ * ftanh(cn);
            }
        __syncthreads();   // everyone done reading hs / xs
#pragma unroll
        for (int r = 0; r < 8; ++r)
            *(float2*)&hs[r0 + r][hc0] = make_float2(hnew[r][0], hnew[r][1]);
        if (tid < 96 && t + 1 < TT)
            xs[xr][xk] = x[(b0 + xr) * (TT * INF) + (t + 1) * INF + xk];
        __syncthreads();   // new hs / xs visible
    }

    // final h -> global (coalesced; hs layout matches g_h rows)
    for (int i = tid; i < ROWS * HH; i += THR)
        g_h[b0 * HH + i] = ((float*)hs)[i];
}

// ---------------- BN stats (two-pass, per feature) ----------------
__global__ void bn_stats(const float* __restrict__ gamma,
                         const float* __restrict__ beta) {
    const int j = blockIdx.x;     // feature 0..127
    const int tid = threadIdx.x;
    __shared__ float red[256];
    __shared__ float mean_s;

    float s = 0.0f;
    for (int r = tid; r < BB; r += 256) s += g_h[r * HH + j];
    red[tid] = s; __syncthreads();
    for (int o = 128; o > 0; o >>= 1) { if (tid < o) red[tid] += red[tid + o]; __syncthreads(); }
    if (tid == 0) mean_s = red[0] * (1.0f / BB);
    __syncthreads();
    const float m = mean_s;

    float s2 = 0.0f;
    for (int r = tid; r < BB; r += 256) { float d = g_h[r * HH + j] - m; s2 += d * d; }
    red[tid] = s2; __syncthreads();
    for (int o = 128; o > 0; o >>= 1) { if (tid < o) red[tid] += red[tid + o]; __syncthreads(); }
    if (tid == 0) {
        float var  = red[0] * (1.0f / BB);
        float rstd = rsqrtf(var + 1e-5f);
        g_scale[j] = rstd * gamma[j];
        g_shift[j] = beta[j] - m * rstd * gamma[j];
    }
}

// ---------------- BN apply + LeakyReLU + FC + sigmoid ----------------
__global__ void out_kernel(const float* __restrict__ fcw,
                           const float* __restrict__ fcb,
                           float* __restrict__ out) {
    const int lane = threadIdx.x & 31;
    const int warp = threadIdx.x >> 5;
    const int b = blockIdx.x * 4 + warp;   // block = 128 thr = 4 rows
    float acc = 0.0f;
#pragma unroll
    for (int q = 0; q < 4; ++q) {
        int j = lane + q * 32;
        float v = __fmaf_rn(g_h[b * HH + j], g_scale[j], g_shift[j]);
        v = (v >= 0.0f) ? v : 0.01f * v;            // LeakyReLU
        acc = __fmaf_rn(v, fcw[j], acc);
    }
#pragma unroll
    for (int o = 16; o > 0; o >>= 1) acc += __shfl_xor_sync(0xffffffffu, acc, o);
    if (lane == 0) out[b] = fsigmoid(acc + fcb[0]);
}

// ---------------- launch ----------------
extern "C" void kernel_launch(void* const* d_in, const int* in_sizes, int n_in,
                              void* d_out, int out_size) {
    const float* x     = (const float*)d_in[0];
    const float* W_ih  = (const float*)d_in[1];
    const float* W_hh  = (const float*)d_in[2];
    const float* b_ih  = (const float*)d_in[3];
    const float* b_hh  = (const float*)d_in[4];
    const float* gamma = (const float*)d_in[5];
    const float* beta  = (const float*)d_in[6];
    const float* fc_w  = (const float*)d_in[7];
    const float* fc_b  = (const float*)d_in[8];
    float* out = (float*)d_out;

    prep_kernel<<<(HH * G4 + 255) / 256, 256>>>(W_hh, b_ih, b_hh);
    lstm_main<<<CTAS, THR>>>(x, W_ih);
    bn_stats<<<HH, 256>>>(gamma, beta);
    out_kernel<<<BB / 4, 128>>>(fc_w, fc_b, out);
}